// round 17
// baseline (speedup 1.0000x reference)
#include <cuda_runtime.h>
#include <cuda_fp16.h>
#include <cstdint>

// Problem constants
#define T_STEPS 256
#define BATCH   128
#define HID     1024
#define LAT     128
#define PIECE   128

// CTA = (batch half bh = blk>>6, unit group ug = blk&63): 64 batch rows x
// (16 hidden units = 64 gate cols) + 2 FC cols (p = ug*2, ug*2+1).
#define NBLK 128
#define NHALF 64             // CTAs per independent batch-half barrier group
#define NTHR 256             // 8 warps = 4 row-groups x 2 n-halves
#define KCH  64              // k per streamed chunk
#define NCHUNK 16
#define NSTG 8               // A staging stages per row-group
#define NINFL 6              // cp.async groups in flight

// B: 66 rows (64 gate cols + 2 FC) x 1024 k fp16, row stride 1032 elems
#define BSTR 1032
#define OFF_B 0                            // 66*1032*2 = 136224 B
#define OFF_A 136224                       // 4 row-group regions, 8 stages
#define ASTRB 144                          // A row bytes: 64 k * 2 + 16 pad
#define A_STG  (16 * ASTRB)                // 2304 B per stage (16 rows)
#define A_RREG (NSTG * A_STG)              // 18432 B per row-group
#define OFF_MISC (OFF_A + 4 * A_RREG)      // 209952 ; bsum[64]
#define SMEM_BYTES (OFF_MISC + 512)        // 210464

typedef unsigned long long ull;

// Persistent state: h in fp16 (2^-11 precision, |h|<=1)
__device__ __half g_h16[2][BATCH * HID];   // [time buf][b][k]
__device__ unsigned g_bar2[2];             // per-half monotonic barrier counters

// ---------------- helpers ----------------
__device__ __forceinline__ uint32_t smem_u32(const void* p) {
    uint32_t a;
    asm("{ .reg .u64 t; cvta.to.shared.u64 t, %1; cvt.u32.u64 %0, t; }"
        : "=r"(a) : "l"(p));
    return a;
}
__device__ __forceinline__ void cp_async16(uint32_t sdst, const void* gsrc) {
    asm volatile("cp.async.cg.shared.global [%0], [%1], 16;\n" :: "r"(sdst), "l"(gsrc));
}
__device__ __forceinline__ void cp_commit() { asm volatile("cp.async.commit_group;\n"); }
__device__ __forceinline__ void cp_waitN(int n) {
    switch (n) {
    case 0: asm volatile("cp.async.wait_group 0;\n"); break;
    case 1: asm volatile("cp.async.wait_group 1;\n"); break;
    case 2: asm volatile("cp.async.wait_group 2;\n"); break;
    case 3: asm volatile("cp.async.wait_group 3;\n"); break;
    case 4: asm volatile("cp.async.wait_group 4;\n"); break;
    case 5: asm volatile("cp.async.wait_group 5;\n"); break;
    default: asm volatile("cp.async.wait_group 6;\n"); break;
    }
}
// named barrier over one row-group pair (64 threads); ids 1..4
__device__ __forceinline__ void bar_pair(int rg) {
    asm volatile("bar.sync %0, 64;" :: "r"(1 + rg) : "memory");
}

__device__ __forceinline__ void ldsm4(uint32_t* r, uint32_t addr) {
    asm volatile("ldmatrix.sync.aligned.m8n8.x4.shared.b16 {%0,%1,%2,%3}, [%4];"
                 : "=r"(r[0]), "=r"(r[1]), "=r"(r[2]), "=r"(r[3]) : "r"(addr));
}
__device__ __forceinline__ void ldsm2(uint32_t* r, uint32_t addr) {
    asm volatile("ldmatrix.sync.aligned.m8n8.x2.shared.b16 {%0,%1}, [%2];"
                 : "=r"(r[0]), "=r"(r[1]) : "r"(addr));
}
// mma.sync m16n8k16 row.col f32.f16.f16.f32
__device__ __forceinline__ void mma16816(float* d, const uint32_t* a, const uint32_t* b) {
    asm volatile(
        "mma.sync.aligned.m16n8k16.row.col.f32.f16.f16.f32 "
        "{%0,%1,%2,%3}, {%4,%5,%6,%7}, {%8,%9}, {%0,%1,%2,%3};"
        : "+f"(d[0]), "+f"(d[1]), "+f"(d[2]), "+f"(d[3])
        : "r"(a[0]), "r"(a[1]), "r"(a[2]), "r"(a[3]), "r"(b[0]), "r"(b[1]));
}
__device__ __forceinline__ float sigf(float x) { return 1.0f / (1.0f + __expf(-x)); }
// fast tanh via MUFU EX2 path: tanh(x) = 1 - 2/(e^{2x}+1)
__device__ __forceinline__ float tanhfast(float x) {
    return 1.0f - 2.0f / (__expf(2.0f * x) + 1.0f);
}

// Per-half grid barrier (64 co-resident CTAs of one batch half; the two
// halves are fully independent). Monotonic counter, graph-replay safe.
__device__ __forceinline__ void grid_bar_half(int bh) {
    __threadfence();
    __syncthreads();
    if (threadIdx.x == 0) {
        unsigned my = atomicAdd(&g_bar2[bh], 1u);
        unsigned target = my - (my % NHALF) + NHALF;
        while (*(volatile unsigned*)&g_bar2[bh] < target) { __nanosleep(20); }
        __threadfence();
    }
    __syncthreads();
}

// ---------------- persistent mma.sync kernel ----------------
// Per step, per CTA: D[64 x 66] = h[rb..rb+63, 0..1023] . B^T
//   B row n<64: n = lu*4+g -> w_hh[g*HID + ug*16 + lu][:]
//   B rows 64,65 -> W_fc[ug*2 + 0/1][:]
// h fp16, B fp16: D = A.B (fp32 accum)
// Warps: rg = wid>>1 (rows rg*16..+15), nh = wid&1 (cols nh*32..+31 + FC 64+nh)
// Row-group pair shares staged A; per-chunk named barrier.
extern "C" __global__ void __launch_bounds__(NTHR, 1)
lstm_mma_kernel(const float* __restrict__ z,
                const float* __restrict__ w_ih,
                const float* __restrict__ w_hh,
                const float* __restrict__ b_ih,
                const float* __restrict__ b_hh,
                const float* __restrict__ W_fc,
                const float* __restrict__ b_fc,
                float* __restrict__ out)
{
    extern __shared__ char smem[];
    const uint32_t sbase = smem_u32(smem);
    float* bsum = (float*)(smem + OFF_MISC);     // [64] gate biases
    float* Xg   = (float*)(smem + OFF_A);        // [64][64] f32, t=0 only (alias)

    const int tid  = threadIdx.x;
    const int blk  = blockIdx.x;
    const int bh   = blk >> 6;       // batch half
    const int ug   = blk & 63;       // unit group (16 units)
    const int rb   = bh * 64;        // CTA's first batch row
    const int wid  = tid >> 5;
    const int lane = tid & 31;
    const int rg   = wid >> 1;       // row group: rows rg*16..+15 (local)
    const int nh   = wid & 1;        // n-half: cols nh*32..+31, FC row 64+nh

    // ---------- prologue: build B (fp16), 66 rows ----------
    for (int e = tid; e < 66 * HID; e += NTHR) {
        int n = e >> 10, k = e & 1023;
        float x;
        if (n < 64) {
            int lu = n >> 2, g = n & 3;
            x = w_hh[(size_t)(g * HID + ug * 16 + lu) * HID + k];
        } else {
            x = W_fc[(size_t)(ug * 2 + (n - 64)) * HID + k];
        }
        *(__half*)(smem + OFF_B + ((size_t)n * BSTR + k) * 2) = __float2half_rn(x);
    }
    if (tid < 64) {
        int lu = tid >> 2, g = tid & 3;
        bsum[tid] = b_ih[g * HID + ug * 16 + lu] + b_hh[g * HID + ug * 16 + lu];
    }
    const float bfc = b_fc[ug * 2 + nh];

    // Step-0 input gates: Xg[n][bl] = z[rb+bl,:] . w_ih[row(n),:]
    for (int d = tid; d < 64 * 64; d += NTHR) {
        int n = d >> 6, bl = d & 63;
        int lu = n >> 2, g = n & 3;
        const float* wi = w_ih + (size_t)(g * HID + ug * 16 + lu) * LAT;
        const float* zb = z + (size_t)(rb + bl) * LAT;
        float s = 0.f;
        #pragma unroll 4
        for (int l = 0; l < LAT; ++l) s += zb[l] * wi[l];
        Xg[n * 64 + bl] = s;
    }
    __syncthreads();

    // staging + ldmatrix lane offsets
    const uint32_t rbase = sbase + OFF_A + (uint32_t)rg * A_RREG;
    const uint32_t aoff  = (uint32_t)((lane & 15) * ASTRB + (lane >> 4) * 16);
    // B ldsm4-pair: row = nh*32 + (lane>>4)*8 + (lane&7), kseg = (lane>>3)&1
    const uint32_t boffJ = (uint32_t)((nh * 32 + (lane >> 4) * 8 + (lane & 7))
                                      * (BSTR * 2) + ((lane >> 3) & 1) * 16);
    // FC ldsm2: all rows clamped to row 64+nh (cols all equal y)
    const uint32_t boff4 = (uint32_t)((64 + nh) * (BSTR * 2) + ((lane >> 3) & 1) * 16);

    // epilogue identity: pair (lane, lane^1); par selects local row r / r+8
    const int par  = lane & 1;
    const int rloc = rg * 16 + (lane >> 2) + 8 * par;   // local batch row
    const int rgl  = rb + rloc;                         // global batch row
    const int uo   = (lane >> 1) & 1;                   // unit parity in n8 tile

    // hoist this thread's 16 gate biases into registers
    float bso[4][4];
    #pragma unroll
    for (int j = 0; j < 4; ++j) {
        int lu = nh * 8 + 2 * j + uo;
        #pragma unroll
        for (int g = 0; g < 4; ++g) bso[j][g] = bsum[lu * 4 + g];
    }

    float cst[4] = {0.f, 0.f, 0.f, 0.f};  // c-state: local units nh*8+2j+uo, row rgl

    for (int t = 0; t <= T_STEPS; ++t) {
        float d[5][4];
        #pragma unroll
        for (int j = 0; j < 5; ++j)
            #pragma unroll
            for (int q = 0; q < 4; ++q) d[j][q] = 0.f;

        if (t >= 1) {
            const __half* hsrc = g_h16[t & 1];

            // warp nh loads rows nh*8..nh*8+7 of the row-group's 16-row stage
            #define PREFETCH(m) do {                                          \
                uint32_t st = rbase + ((m) & (NSTG - 1)) * A_STG;             \
                size_t kb = (size_t)(m) * KCH;                                \
                _Pragma("unroll")                                             \
                for (int s = 0; s < 2; ++s) {                                 \
                    int mm = s * 32 + lane; int rr = mm >> 3, sg = mm & 7;    \
                    cp_async16(st + (nh * 8 + rr) * ASTRB + sg * 16,          \
                               hsrc + (size_t)(rb + rg * 16 + nh * 8 + rr) * HID \
                                    + kb + sg * 8);                           \
                }                                                             \
                cp_commit();                                                  \
            } while (0)

            #pragma unroll
            for (int m = 0; m < NINFL; ++m) PREFETCH(m);

            for (int c = 0; c < NCHUNK; ++c) {
                if (c + NINFL < NCHUNK) PREFETCH(c + NINFL);
                int pend = NCHUNK - 1 - c; if (pend > NINFL) pend = NINFL;
                cp_waitN(pend);          // own half of stage c landed
                bar_pair(rg);            // peer's half landed too

                const uint32_t aB = rbase + (c & (NSTG - 1)) * A_STG + aoff;
                const uint32_t kb = (uint32_t)c * (KCH * 2);

                #pragma unroll
                for (int kk = 0; kk < 4; ++kk) {      // 4 k16 sub-tiles
                    uint32_t a[4];
                    ldsm4(a, aB + kk * 32);

                    #pragma unroll
                    for (int jb = 0; jb < 2; ++jb) {  // local n8 tile pairs
                        uint32_t bhv[4];
                        uint32_t ba = sbase + OFF_B + boffJ
                                    + (uint32_t)(jb * 16) * (BSTR * 2)
                                    + kb + kk * 32;
                        ldsm4(bhv, ba);
                        mma16816(d[jb * 2],     a, bhv);
                        mma16816(d[jb * 2 + 1], a, bhv + 2);
                    }
                    {                                 // FC row (clamped)
                        uint32_t bhv[2];
                        ldsm2(bhv, sbase + OFF_B + boff4 + kb + kk * 32);
                        mma16816(d[4], a, bhv);
                    }
                }
            }
            #undef PREFETCH
        }

        // ---------- epilogue ----------
        if (t >= 1 && uo == 0) {
            // FC tile: all cols equal y (clamped B rows) -> no shfl needed
            float yv = par ? d[4][2] : d[4][0];
            out[(size_t)rgl * (T_STEPS * PIECE) + (size_t)(t - 1) * PIECE
                + (ug * 2 + nh)] = yv + bfc;
        }

        if (t < T_STEPS) {
            __half hh[4];
            #pragma unroll
            for (int j = 0; j < 4; ++j) {
                int lu = nh * 8 + 2 * j + uo;         // local unit 0..15
                float gv[4];
                if (t == 0) {
                    #pragma unroll
                    for (int g = 0; g < 4; ++g)
                        gv[g] = Xg[(lu * 4 + g) * 64 + rloc] + bso[j][g];
                } else {
                    float x0 = __shfl_xor_sync(0xffffffffu, d[j][0], 1);
                    float x1 = __shfl_xor_sync(0xffffffffu, d[j][1], 1);
                    float x2 = __shfl_xor_sync(0xffffffffu, d[j][2], 1);
                    float x3 = __shfl_xor_sync(0xffffffffu, d[j][3], 1);
                    if (par == 0) {          // row r: own = gates 0,1; partner = 2,3
                        gv[0] = d[j][0]; gv[1] = d[j][1]; gv[2] = x0; gv[3] = x1;
                    } else {                 // row r+8: partner = 0,1; own = 2,3
                        gv[0] = x2; gv[1] = x3; gv[2] = d[j][2]; gv[3] = d[j][3];
                    }
                    #pragma unroll
                    for (int g = 0; g < 4; ++g) gv[g] += bso[j][g];
                }
                float i_ = sigf(gv[0]), f_ = sigf(gv[1]);
                float g_ = tanhfast(gv[2]), o_ = sigf(gv[3]);
                float cc = f_ * cst[j] + i_ * g_;
                cst[j] = cc;
                hh[j] = __float2half_rn(o_ * tanhfast(cc));
            }
            // store h_t: k = ug*16 + nh*8 + 2j + uo, row rgl
            __half* dh = g_h16[(t + 1) & 1] + (size_t)rgl * HID
                       + ug * 16 + nh * 8 + uo;
            #pragma unroll
            for (int j = 0; j < 4; ++j) dh[2 * j] = hh[j];

            grid_bar_half(bh);   // h_t (this half) visible before step t+1
        }
    }
}

// ---------------- launch ----------------
extern "C" void kernel_launch(void* const* d_in, const int* in_sizes, int n_in,
                              void* d_out, int out_size)
{
    // metadata order: current_batch_size, z, w_ih, w_hh, b_ih, b_hh, W_fc, b_fc
    int off = (n_in >= 8) ? 1 : 0;
    const float* z    = (const float*)d_in[off + 0];
    const float* w_ih = (const float*)d_in[off + 1];
    const float* w_hh = (const float*)d_in[off + 2];
    const float* b_ih = (const float*)d_in[off + 3];
    const float* b_hh = (const float*)d_in[off + 4];
    const float* W_fc = (const float*)d_in[off + 5];
    const float* b_fc = (const float*)d_in[off + 6];

    cudaFuncSetAttribute(lstm_mma_kernel,
                         cudaFuncAttributeMaxDynamicSharedMemorySize, SMEM_BYTES);

    lstm_mma_kernel<<<NBLK, NTHR, SMEM_BYTES>>>(
        z, w_ih, w_hh, b_ih, b_hh, W_fc, b_fc, (float*)d_out);
}